// round 6
// baseline (speedup 1.0000x reference)
#include <cuda_runtime.h>
#include <cstdint>

#define BSZ 256
#define TLEN 512
#define KTAG 48
#define KK (KTAG*KTAG)          // 2304 floats per (b,t) tile
#define START_TAG 46
#define END_TAG 47
#define NY 4
#define ROWS 12                 // rows per thread
#define NTHREADS 192
#define L2E 1.44269504088896f
#define LN2 0.6931471805599453f

__device__ float g_partial[BSZ];
__device__ unsigned int g_count;   // zero-init; reset by reducing CTA

__device__ __forceinline__ float fast_ex2(float x) {
    float r; asm("ex2.approx.ftz.f32 %0, %1;" : "=f"(r) : "f"(x)); return r;
}
__device__ __forceinline__ float fast_lg2(float x) {
    float r; asm("lg2.approx.ftz.f32 %0, %1;" : "=f"(r) : "f"(x)); return r;
}
__device__ __forceinline__ float fast_rcp(float x) {
    float r; asm("rcp.approx.ftz.f32 %0, %1;" : "=f"(r) : "f"(x)); return r;
}

// One recursion step. VA = esc of tile T (ready); VB = raw tile T+1 (convert here);
// after the dot, VA's registers are refilled with raw tile T+3. TVA = true-path
// gather value for tile T (tid 0 only), refilled with tile T+3's gather.
#define STEP(T, VA, VB, TVA)                                                     \
  {                                                                              \
    __syncthreads();                        /* eag_T published */                \
    const float* eg = eag2[(T) & 1];                                             \
    const float e0v = eg[0];                                                     \
    const float rc  = fast_rcp(e0v);                                             \
    const float lgv = fast_lg2(e0v);                                             \
    float a0 = VA[0] * eg[i0 + 0];                                               \
    float a1 = VA[1] * eg[i0 + 1];                                               \
    float a2 = VA[2] * eg[i0 + 2];                                               \
    float a3 = VA[3] * eg[i0 + 3];                                               \
    _Pragma("unroll")                                                            \
    for (int k = 4; k < ROWS; k += 4) {                                          \
      a0 = fmaf(VA[k + 0], eg[i0 + k + 0], a0);                                  \
      a1 = fmaf(VA[k + 1], eg[i0 + k + 1], a1);                                  \
      a2 = fmaf(VA[k + 2], eg[i0 + k + 2], a2);                                  \
      a3 = fmaf(VA[k + 3], eg[i0 + k + 3], a3);                                  \
    }                                                                            \
    float s = (a0 + a1) + (a2 + a3);                                             \
    if ((T) + 3 < len) {                    /* refill VA with raw tile T+3 */    \
      const float* p = tb0 + (size_t)((T) + 3) * KK;                             \
      _Pragma("unroll")                                                          \
      for (int k = 0; k < ROWS; ++k) VA[k] = __ldg(p + k * KTAG);                \
      if (tid == 0) {                                                            \
        true_sum += TVA;                                                         \
        TVA = __ldg(base + (size_t)((T) + 3) * KK + tgt_s[(T) + 3]);             \
      }                                                                          \
    } else if (tid == 0) { true_sum += TVA; }                                    \
    _Pragma("unroll")                       /* raw tile T+1 -> esc */            \
    for (int k = 0; k < ROWS; ++k) VB[k] = fast_ex2(VB[k] * L2E);                \
    s += __shfl_xor_sync(0xffffffffu, s, 1);                                     \
    s += __shfl_xor_sync(0xffffffffu, s, 2);                                     \
    if (y == 0) eag2[((T) + 1) & 1][j] = s * rc;                                 \
    N += lgv;                                                                    \
  }

__global__ __launch_bounds__(NTHREADS, 2)
void crf_fwd_kernel(const float* __restrict__ scores,
                    const int* __restrict__ targets,
                    const int* __restrict__ lengths,
                    float* __restrict__ out)
{
    __shared__ float eag2[2][KTAG];     // exp-domain forward potentials, ping-pong
    __shared__ int   tgt_s[TLEN];

    const int bid = blockIdx.x;
    // SM k classically hosts bids k and k+148 -> pair batch s with 255-s (lengths sorted desc).
    const int b = (bid < 148) ? bid : (403 - bid);

    const int tid = threadIdx.x;
    const int j   = tid >> 2;           // column 0..47
    const int y   = tid & 3;            // row-group 0..3 (4 partials within one warp)
    const int i0  = y * ROWS;
    const int len = lengths[b];

    const float* base = scores + (size_t)b * TLEN * KK;
    const float* tb0  = base + i0 * KTAG + j;   // this thread's element base in tile 0

    for (int t = tid; t < len; t += NTHREADS)
        tgt_s[t] = targets[b * TLEN + t];

    __syncthreads();                    // tgt_s visible

    // t = 0: eag_1[j] = 2^(log2e * score[0][START][j])
    if (y == 0)
        eag2[1][j] = fast_ex2(__ldg(base + START_TAG * KTAG + j) * L2E);

    // Prologue: prime register pipeline with tiles 1,2,3 (clamped addresses).
    float v0[ROWS], v1[ROWS], v2[ROWS];
    {
        const int c1 = (1 < len) ? 1 : (len - 1);
        const int c2 = (2 < len) ? 2 : (len - 1);
        const int c3 = (3 < len) ? 3 : (len - 1);
        const float* p1 = tb0 + (size_t)c1 * KK;
        const float* p2 = tb0 + (size_t)c2 * KK;
        const float* p3 = tb0 + (size_t)c3 * KK;
        #pragma unroll
        for (int k = 0; k < ROWS; ++k) {
            v1[k] = __ldg(p1 + k * KTAG);   // tile 1 (slot 1)
            v2[k] = __ldg(p2 + k * KTAG);   // tile 2 (slot 2)
            v0[k] = __ldg(p3 + k * KTAG);   // tile 3 (slot 0)
        }
        #pragma unroll
        for (int k = 0; k < ROWS; ++k)      // tile 1 raw -> esc
            v1[k] = fast_ex2(v1[k] * L2E);
    }

    // True-path gather pipeline (tid 0 only)
    float true_sum = 0.0f, tv1 = 0.0f, tv2 = 0.0f, tv0 = 0.0f;
    if (tid == 0) {
        true_sum = __ldg(base + tgt_s[0]);
        if (1 < len) tv1 = __ldg(base + (size_t)1 * KK + tgt_s[1]);
        if (2 < len) tv2 = __ldg(base + (size_t)2 * KK + tgt_s[2]);
        if (3 < len) tv0 = __ldg(base + (size_t)3 * KK + tgt_s[3]);
    }

    float N = 0.0f;
    int t = 1;
    for (; t + 2 < len; t += 3) {
        STEP(t,     v1, v2, tv1);
        STEP(t + 1, v2, v0, tv2);
        STEP(t + 2, v0, v1, tv0);
    }
    if (t < len) { STEP(t, v1, v2, tv1); ++t; }
    if (t < len) { STEP(t, v2, v0, tv2); }

    __syncthreads();
    if (tid == 0)
        g_partial[b] = (fast_lg2(eag2[len & 1][END_TAG]) + N) * LN2 - true_sum;

    // Last-arriving CTA reduces (deterministic fixed-order tree)
    if (tid < 32) {
        unsigned done = 0;
        if (tid == 0) {
            __threadfence();
            done = atomicAdd(&g_count, 1u);
        }
        done = __shfl_sync(0xffffffffu, done, 0);
        if (done == BSZ - 1) {
            __threadfence();
            const volatile float* gp = g_partial;
            float s = 0.0f;
            #pragma unroll
            for (int k = 0; k < BSZ / 32; ++k) s += gp[tid + 32 * k];
            s += __shfl_xor_sync(0xffffffffu, s, 16);
            s += __shfl_xor_sync(0xffffffffu, s, 8);
            s += __shfl_xor_sync(0xffffffffu, s, 4);
            s += __shfl_xor_sync(0xffffffffu, s, 2);
            s += __shfl_xor_sync(0xffffffffu, s, 1);
            if (tid == 0) {
                out[0] = s / (float)BSZ;
                g_count = 0;    // reset for next graph replay
            }
        }
    }
}

extern "C" void kernel_launch(void* const* d_in, const int* in_sizes, int n_in,
                              void* d_out, int out_size)
{
    const float* scores  = (const float*)d_in[0];
    const int*   targets = (const int*)d_in[1];
    const int*   lengths = (const int*)d_in[2];
    float* out = (float*)d_out;

    crf_fwd_kernel<<<BSZ, NTHREADS>>>(scores, targets, lengths, out);
}

// round 7
// speedup vs baseline: 1.7590x; 1.7590x over previous
#include <cuda_runtime.h>
#include <cstdint>

#define BSZ 256
#define TLEN 512
#define KTAG 48
#define KK 2304                 // floats per (b,t) tile
#define PAD 52                  // padded row stride (floats); conflict-free for rows y+4m
#define TILE_F (KTAG*PAD)       // 2496 floats per padded tile
#define START_TAG 46
#define END_TAG 47
#define NTHREADS 192
#define NM 12                   // rows per thread (rows y + 4m, m=0..11)
#define NBUF 8
#define CPR 12                  // 16B chunks per tile row
#define L2E 1.44269504088896f
#define LN2 0.6931471805599453f

__device__ float g_partial[BSZ];
__device__ unsigned int g_count;   // zero-init; reset by reducing CTA

__device__ __forceinline__ void cp16(uint32_t dst_smem, const void* src) {
    asm volatile("cp.async.cg.shared.global [%0], [%1], 16;" :: "r"(dst_smem), "l"(src));
}
__device__ __forceinline__ void cp_commit() {
    asm volatile("cp.async.commit_group;" ::: "memory");
}
template<int N>
__device__ __forceinline__ void cp_wait() {
    asm volatile("cp.async.wait_group %0;" :: "n"(N) : "memory");
}
__device__ __forceinline__ float fast_ex2(float x) {
    float r; asm("ex2.approx.ftz.f32 %0, %1;" : "=f"(r) : "f"(x)); return r;
}
__device__ __forceinline__ float fast_lg2(float x) {
    float r; asm("lg2.approx.ftz.f32 %0, %1;" : "=f"(r) : "f"(x)); return r;
}
__device__ __forceinline__ float fast_rcp(float x) {
    float r; asm("rcp.approx.ftz.f32 %0, %1;" : "=f"(r) : "f"(x)); return r;
}

// One recursion step for tile T. P = T&1 (parity), SNXT = (T+1)&7, SPRE = (T+6)&7.
// esc[] holds 2^(L2E*score_T[row y+4m][j]) on entry; refilled with tile T+1 on exit.
#define STEP(T, P, SNXT, SPRE)                                                   \
  {                                                                              \
    __syncthreads();                               /* eag_T published */         \
    const float* eg = eagm + (P) * KTAG;                                         \
    const float e0v = eg[0];                                                     \
    const float rc  = fast_rcp(e0v);                                             \
    const float lgv = fast_lg2(e0v);                                             \
    float a0 = esc[0] * eg[y +  0], a1 = esc[1] * eg[y +  4];                    \
    float a2 = esc[2] * eg[y +  8], a3 = esc[3] * eg[y + 12];                    \
    a0 = fmaf(esc[4],  eg[y + 16], a0); a1 = fmaf(esc[5],  eg[y + 20], a1);      \
    a2 = fmaf(esc[6],  eg[y + 24], a2); a3 = fmaf(esc[7],  eg[y + 28], a3);      \
    a0 = fmaf(esc[8],  eg[y + 32], a0); a1 = fmaf(esc[9],  eg[y + 36], a1);      \
    a2 = fmaf(esc[10], eg[y + 40], a2); a3 = fmaf(esc[11], eg[y + 44], a3);      \
    float sdot = (a0 + a1) + (a2 + a3);                                          \
    sdot += __shfl_xor_sync(0xffffffffu, sdot, 1);                               \
    sdot += __shfl_xor_sync(0xffffffffu, sdot, 2);                               \
    if (y == 0) eagm[((P) ^ 1) * KTAG + j] = sdot * rc;                          \
    N += lgv;                                                                    \
    if (tid == 0) true_sum += tval;                                              \
    if ((T) + 6 < len) {                           /* prefetch tile T+6 */       \
      uint32_t d = sbase + (uint32_t)(SPRE) * (TILE_F * 4);                      \
      cp16(d + d0, srcp + s0); cp16(d + d1, srcp + s1); cp16(d + d2, srcp + s2); \
    }                                                                            \
    srcp += KK * 4;                                                              \
    cp_commit();                                                                 \
    cp_wait<4>();                                  /* tile T+1 resident */       \
    if ((T) + 1 < len) {                           /* refill esc, tval */        \
      const float* rp = buf + (SNXT) * TILE_F + ro;                              \
      _Pragma("unroll")                                                          \
      for (int m = 0; m < NM; ++m) esc[m] = fast_ex2(rp[m * 4 * PAD] * L2E);     \
      if (tid == 0) tval = buf[(SNXT) * TILE_F + tgt_s[(T) + 1]];                \
    }                                                                            \
  }

__global__ __launch_bounds__(NTHREADS, 2)
void crf_fwd_kernel(const float* __restrict__ scores,
                    const int* __restrict__ targets,
                    const int* __restrict__ lengths,
                    float* __restrict__ out)
{
    extern __shared__ float sdyn[];
    float* buf   = sdyn;                          // NBUF * TILE_F
    float* eagm  = buf + NBUF * TILE_F;           // 2 * KTAG (exp-domain agg)
    int*   tgt_s = (int*)(eagm + 2 * KTAG);       // TLEN

    const int bid = blockIdx.x;
    // SM k classically hosts bids k and k+148 -> pair batch s with 255-s (lengths sorted desc).
    const int b = (bid < 148) ? bid : (403 - bid);

    const int tid = threadIdx.x;
    const int j   = tid >> 2;            // column 0..47
    const int y   = tid & 3;             // row-group 0..3 (partials in-warp, 2 shuffles)
    const int len = lengths[b];

    const float* base = scores + (size_t)b * TLEN * KK;

    for (int t = tid; t < len; t += NTHREADS) {
        int tg = targets[b * TLEN + t];
        tgt_s[t] = (tg / KTAG) * PAD + (tg % KTAG);
    }

    // cp.async: exactly 3 chunks per thread (576 = 3*192)
    const uint32_t sbase = (uint32_t)__cvta_generic_to_shared(buf);
    const int c0 = tid, c1 = tid + NTHREADS, c2 = tid + 2 * NTHREADS;
    const uint32_t d0 = (uint32_t)((c0 / CPR) * (PAD * 4) + (c0 % CPR) * 16);
    const uint32_t d1 = (uint32_t)((c1 / CPR) * (PAD * 4) + (c1 % CPR) * 16);
    const uint32_t d2 = (uint32_t)((c2 / CPR) * (PAD * 4) + (c2 % CPR) * 16);
    const uint32_t s0 = (uint32_t)c0 * 16, s1 = (uint32_t)c1 * 16, s2 = (uint32_t)c2 * 16;
    const int ro = y * PAD + j;          // read base offset (rows y+4m at +m*4*PAD)

    // prologue: prime tiles 0..5 (6 commits, counts fixed)
    #pragma unroll
    for (int k = 0; k < 6; ++k) {
        if (k < len) {
            const char* s = (const char*)(base + (size_t)k * KK);
            uint32_t d = sbase + (uint32_t)k * (TILE_F * 4);
            cp16(d + d0, s + s0); cp16(d + d1, s + s1); cp16(d + d2, s + s2);
        }
        cp_commit();
    }
    cp_wait<4>();            // tiles 0,1 complete (own groups)
    __syncthreads();         // cross-thread visibility of tiles 0,1 + tgt_s

    // t = 0: eag_1[j] = 2^(L2E * score[0][START][j])   (parity 1)
    if (y == 0)
        eagm[KTAG + j] = fast_ex2(buf[START_TAG * PAD + j] * L2E);

    float esc[NM];
    if (len > 1) {
        const float* rp = buf + TILE_F + ro;   // tile 1, slot 1
        #pragma unroll
        for (int m = 0; m < NM; ++m) esc[m] = fast_ex2(rp[m * 4 * PAD] * L2E);
    }
    float tval = 0.0f, true_sum = 0.0f;
    if (tid == 0) {
        true_sum = buf[tgt_s[0]];
        if (len > 1) tval = buf[TILE_F + tgt_s[1]];
    }
    const char* srcp = (const char*)(base + (size_t)6 * KK);
    float N = 0.0f;

    int t = 1;
    for (; t + 7 < len; t += 8) {          // t ≡ 1 (mod 8): all slots/parities constant
        STEP(t,     1, 2, 7)
        STEP(t + 1, 0, 3, 0)
        STEP(t + 2, 1, 4, 1)
        STEP(t + 3, 0, 5, 2)
        STEP(t + 4, 1, 6, 3)
        STEP(t + 5, 0, 7, 4)
        STEP(t + 6, 1, 0, 5)
        STEP(t + 7, 0, 1, 6)
    }
    for (; t < len; ++t) {                 // remainder: runtime slots (≤7 iters)
        STEP(t, (t & 1), ((t + 1) & 7), ((t + 6) & 7))
    }

    __syncthreads();
    if (tid == 0)
        g_partial[b] = (fast_lg2(eagm[(len & 1) * KTAG + END_TAG]) + N) * LN2 - true_sum;

    // last-arriving CTA reduces (deterministic fixed-order tree)
    if (tid < 32) {
        unsigned done = 0;
        if (tid == 0) {
            __threadfence();
            done = atomicAdd(&g_count, 1u);
        }
        done = __shfl_sync(0xffffffffu, done, 0);
        if (done == BSZ - 1) {
            __threadfence();
            const volatile float* gp = g_partial;
            float s = 0.0f;
            #pragma unroll
            for (int k = 0; k < BSZ / 32; ++k) s += gp[tid + 32 * k];
            s += __shfl_xor_sync(0xffffffffu, s, 16);
            s += __shfl_xor_sync(0xffffffffu, s, 8);
            s += __shfl_xor_sync(0xffffffffu, s, 4);
            s += __shfl_xor_sync(0xffffffffu, s, 2);
            s += __shfl_xor_sync(0xffffffffu, s, 1);
            if (tid == 0) {
                out[0] = s / (float)BSZ;
                g_count = 0;               // reset for next graph replay
            }
        }
    }
}

extern "C" void kernel_launch(void* const* d_in, const int* in_sizes, int n_in,
                              void* d_out, int out_size)
{
    const float* scores  = (const float*)d_in[0];
    const int*   targets = (const int*)d_in[1];
    const int*   lengths = (const int*)d_in[2];
    float* out = (float*)d_out;

    const int smem_bytes = (NBUF * TILE_F + 2 * KTAG) * 4 + TLEN * 4;
    cudaFuncSetAttribute(crf_fwd_kernel,
                         cudaFuncAttributeMaxDynamicSharedMemorySize, smem_bytes);

    crf_fwd_kernel<<<BSZ, NTHREADS, smem_bytes>>>(scores, targets, lengths, out);
}